// round 6
// baseline (speedup 1.0000x reference)
#include <cuda_runtime.h>
#include <math.h>
#include <float.h>

#define N_NODES 100000
#define N_EDGES 1600000
#define ETOT    (N_EDGES + N_NODES)
#define IN_DIM  256
#define HID     128
#define OUTD    64
#define NEG_SLOPE 0.2f
#define FULLM 0xffffffffu

// ---------------- scratch (static device globals; no allocation) ----------------
static __device__ __align__(128) float g_h1[(size_t)N_NODES * HID];    // x@W1
static __device__ __align__(128) float g_o1[(size_t)N_NODES * HID];    // elu(agg1+b1)
static __device__ __align__(128) float g_h2[(size_t)N_NODES * OUTD];   // o1@W2
static __device__ __align__(128) float g_acc1[(size_t)N_NODES * HID];  // unnormalized agg
static __device__ __align__(128) float g_acc2[(size_t)N_NODES * OUTD];
static __device__ float    g_ssrc[N_NODES];
static __device__ float    g_sdst[N_NODES];
static __device__ unsigned g_m1[N_NODES];   // encoded per-dst max
static __device__ unsigned g_m2[N_NODES];
static __device__ float    g_d1[N_NODES];   // softmax denominators
static __device__ float    g_d2[N_NODES];

// monotone float <-> uint encoding for atomicMax
__device__ __forceinline__ unsigned fenc(float f) {
    unsigned u = __float_as_uint(f);
    return (u & 0x80000000u) ? ~u : (u | 0x80000000u);
}
__device__ __forceinline__ float fdec(unsigned k) {
    unsigned u = (k & 0x80000000u) ? (k ^ 0x80000000u) : ~k;
    return __uint_as_float(u);
}

__device__ __forceinline__ void edge_decode(const int* __restrict__ ei, int t,
                                            int& src, int& dst) {
    if (t < N_EDGES) { src = __ldg(ei + t); dst = __ldg(ei + N_EDGES + t); }
    else             { src = dst = t - N_EDGES; }
}

// ---------------- zero / init everything in one kernel ----------------
__global__ void k_zero_all() {
    int i = blockIdx.x * blockDim.x + threadIdx.x;
    int T = gridDim.x * blockDim.x;
    float4 z = make_float4(0.f, 0.f, 0.f, 0.f);
    for (int j = i; j < N_NODES * (HID / 4); j += T) ((float4*)g_acc1)[j] = z;
    for (int j = i; j < N_NODES * (OUTD / 4); j += T) ((float4*)g_acc2)[j] = z;
    for (int j = i; j < N_NODES; j += T) {
        g_d1[j] = 0.f; g_d2[j] = 0.f; g_m1[j] = 0u; g_m2[j] = 0u;
    }
}

// ---------------- pass 1: per-dst max (thread per edge) ----------------
__global__ void k_max(const int* __restrict__ ei, const float* __restrict__ ssrc,
                      const float* __restrict__ sdst, unsigned* __restrict__ m) {
    int t = blockIdx.x * blockDim.x + threadIdx.x;
    if (t >= ETOT) return;
    int src, dst; edge_decode(ei, t, src, dst);
    float e = ssrc[src] + sdst[dst];
    e = (e > 0.f) ? e : NEG_SLOPE * e;
    atomicMax(&m[dst], fenc(e));
}

// ---------------- pass 2: weighted scatter, warp per edge (F=128) ----------------
__global__ void k_scat128(const int* __restrict__ ei, const float* __restrict__ h,
                          const float* __restrict__ ssrc, const float* __restrict__ sdst,
                          const unsigned* __restrict__ m,
                          float* __restrict__ d, float* __restrict__ acc) {
    int w = (blockIdx.x * blockDim.x + threadIdx.x) >> 5;
    if (w >= ETOT) return;
    int lane = threadIdx.x & 31;
    int src, dst; edge_decode(ei, w, src, dst);
    float e = ssrc[src] + sdst[dst];
    e = (e > 0.f) ? e : NEG_SLOPE * e;
    float wt = __expf(e - fdec(m[dst]));
    if (lane == 0) atomicAdd(&d[dst], wt);
    float4 v = *(const float4*)(h + (size_t)src * HID + lane * 4);
    float* p = acc + (size_t)dst * HID + lane * 4;
    asm volatile("red.global.add.v4.f32 [%0], {%1, %2, %3, %4};"
                 :: "l"(p), "f"(wt * v.x), "f"(wt * v.y), "f"(wt * v.z), "f"(wt * v.w)
                 : "memory");
}

// ---------------- pass 2: weighted scatter, half-warp per edge (F=64) ----------------
__global__ void k_scat64(const int* __restrict__ ei, const float* __restrict__ h,
                         const float* __restrict__ ssrc, const float* __restrict__ sdst,
                         const unsigned* __restrict__ m,
                         float* __restrict__ d, float* __restrict__ acc) {
    int hw = (blockIdx.x * blockDim.x + threadIdx.x) >> 4;   // half-warp = edge
    if (hw >= ETOT) return;
    int l = threadIdx.x & 15;
    int src, dst; edge_decode(ei, hw, src, dst);
    float e = ssrc[src] + sdst[dst];
    e = (e > 0.f) ? e : NEG_SLOPE * e;
    float wt = __expf(e - fdec(m[dst]));
    if (l == 0) atomicAdd(&d[dst], wt);
    float4 v = *(const float4*)(h + (size_t)src * OUTD + l * 4);
    float* p = acc + (size_t)dst * OUTD + l * 4;
    asm volatile("red.global.add.v4.f32 [%0], {%1, %2, %3, %4};"
                 :: "l"(p), "f"(wt * v.x), "f"(wt * v.y), "f"(wt * v.z), "f"(wt * v.w)
                 : "memory");
}

// ---------------- epilogue: normalize + bias (+ELU), streaming ----------------
template<int F, bool ELU>
__global__ void k_fin(const float* __restrict__ acc, const float* __restrict__ d,
                      const float* __restrict__ b, float* __restrict__ out) {
    int i = blockIdx.x * blockDim.x + threadIdx.x;   // over N*F/4 float4s
    if (i >= N_NODES * (F / 4)) return;
    int node = i / (F / 4);
    int f4 = i % (F / 4);
    float inv = 1.f / d[node];
    float4 a = ((const float4*)acc)[i];
    float4 bv = *(const float4*)(b + f4 * 4);
    float4 r;
    r.x = a.x * inv + bv.x;
    r.y = a.y * inv + bv.y;
    r.z = a.z * inv + bv.z;
    r.w = a.w * inv + bv.w;
    if (ELU) {
        r.x = (r.x > 0.f) ? r.x : expm1f(r.x);
        r.y = (r.y > 0.f) ? r.y : expm1f(r.y);
        r.z = (r.z > 0.f) ? r.z : expm1f(r.z);
        r.w = (r.w > 0.f) ? r.w : expm1f(r.w);
    }
    ((float4*)out)[i] = r;
}

// ---------------- GEMM + fused attention-score epilogue (unchanged from R5) ----------------
template<int K, int NCOL, int BM>
__global__ void k_gemm(const float* __restrict__ A, const float* __restrict__ W,
                       float* __restrict__ C,
                       const float* __restrict__ asrc, const float* __restrict__ adst,
                       float* __restrict__ ssrc, float* __restrict__ sdst, int M) {
    constexpr int TN = 4, TM = 8, BK = 16;
    constexpr int TX = NCOL / TN;
    constexpr int ALD = BM + 4;
    constexpr int NC4 = NCOL / 4;
    __shared__ float As[BK][ALD];
    __shared__ float Ws[BK][NCOL];
    const int tid = threadIdx.x;
    const int tx = tid % TX;
    const int ty = tid / TX;
    const int m0 = blockIdx.x * BM;

    float acc[TM][TN];
    #pragma unroll
    for (int r = 0; r < TM; r++)
        #pragma unroll
        for (int n = 0; n < TN; n++) acc[r][n] = 0.f;

    for (int k0 = 0; k0 < K; k0 += BK) {
        #pragma unroll
        for (int i = tid; i < BM * 4; i += 256) {
            int row = i >> 2, kf = (i & 3) * 4;
            float4 v = make_float4(0.f, 0.f, 0.f, 0.f);
            int gr = m0 + row;
            if (gr < M) v = *(const float4*)(A + (size_t)gr * K + k0 + kf);
            As[kf + 0][row] = v.x;
            As[kf + 1][row] = v.y;
            As[kf + 2][row] = v.z;
            As[kf + 3][row] = v.w;
        }
        #pragma unroll
        for (int i = tid; i < BK * NC4; i += 256) {
            int wr = i / NC4, wc = (i % NC4) * 4;
            *(float4*)&Ws[wr][wc] = *(const float4*)(W + (size_t)(k0 + wr) * NCOL + wc);
        }
        __syncthreads();
        #pragma unroll
        for (int kk = 0; kk < BK; kk++) {
            float4 a0 = *(const float4*)&As[kk][ty * TM];
            float4 a1 = *(const float4*)&As[kk][ty * TM + 4];
            float4 wv = *(const float4*)&Ws[kk][tx * TN];
            float a_[TM] = {a0.x, a0.y, a0.z, a0.w, a1.x, a1.y, a1.z, a1.w};
            float w_[TN] = {wv.x, wv.y, wv.z, wv.w};
            #pragma unroll
            for (int r = 0; r < TM; r++)
                #pragma unroll
                for (int n = 0; n < TN; n++)
                    acc[r][n] = fmaf(a_[r], w_[n], acc[r][n]);
        }
        __syncthreads();
    }

    #pragma unroll
    for (int r = 0; r < TM; r++) {
        int row = m0 + ty * TM + r;
        if (row < M) {
            float4 v = make_float4(acc[r][0], acc[r][1], acc[r][2], acc[r][3]);
            *(float4*)(C + (size_t)row * NCOL + tx * TN) = v;
        }
    }

    float4 a1v = *(const float4*)(asrc + tx * TN);
    float4 a2v = *(const float4*)(adst + tx * TN);
    float p1[TM], p2[TM];
    #pragma unroll
    for (int r = 0; r < TM; r++) {
        p1[r] = acc[r][0] * a1v.x + acc[r][1] * a1v.y + acc[r][2] * a1v.z + acc[r][3] * a1v.w;
        p2[r] = acc[r][0] * a2v.x + acc[r][1] * a2v.y + acc[r][2] * a2v.z + acc[r][3] * a2v.w;
    }
    #pragma unroll
    for (int o = TX / 2; o; o >>= 1) {
        #pragma unroll
        for (int r = 0; r < TM; r++) {
            p1[r] += __shfl_xor_sync(FULLM, p1[r], o);
            p2[r] += __shfl_xor_sync(FULLM, p2[r], o);
        }
    }
    if (tx == 0) {
        #pragma unroll
        for (int r = 0; r < TM; r++) {
            int row = m0 + ty * TM + r;
            if (row < M) { ssrc[row] = p1[r]; sdst[row] = p2[r]; }
        }
    }
}

// ---------------- launch ----------------
extern "C" void kernel_launch(void* const* d_in, const int* in_sizes, int n_in,
                              void* d_out, int out_size) {
    const float* x   = (const float*)d_in[0];
    const int*   ei  = (const int*)d_in[1];
    const float* W1  = (const float*)d_in[2];
    const float* a1s = (const float*)d_in[3];
    const float* a1d = (const float*)d_in[4];
    const float* b1  = (const float*)d_in[5];
    const float* W2  = (const float*)d_in[6];
    const float* a2s = (const float*)d_in[7];
    const float* a2d = (const float*)d_in[8];
    const float* b2  = (const float*)d_in[9];
    float* out = (float*)d_out;

    const int g1Blk   = (N_NODES + 63) / 64;       // BM=64
    const int g2Blk   = (N_NODES + 127) / 128;     // BM=128
    const int maxBlk  = (ETOT + 255) / 256;
    const int sc128   = (ETOT * 8 + 255) / 256;    // warp per edge (ETOT*32 threads)
    const int sc64    = (ETOT * 16 + 255) / 256;   // half-warp per edge
    const int fin1Blk = (N_NODES * (HID / 4) + 255) / 256;
    const int fin2Blk = (N_NODES * (OUTD / 4) + 255) / 256;

    k_zero_all<<<2048, 256>>>();                                             // 0
    k_gemm<IN_DIM, HID, 64><<<g1Blk, 256>>>(x, W1, g_h1, a1s, a1d,
                                            g_ssrc, g_sdst, N_NODES);        // 1
    k_max<<<maxBlk, 256>>>(ei, g_ssrc, g_sdst, g_m1);                        // 2
    k_scat128<<<sc128 * 4, 256>>>(ei, g_h1, g_ssrc, g_sdst, g_m1,
                                  g_d1, g_acc1);                             // 3 <- ncu
    k_fin<HID, true><<<fin1Blk, 256>>>(g_acc1, g_d1, b1, g_o1);              // 4
    k_gemm<HID, OUTD, 128><<<g2Blk, 256>>>(g_o1, W2, g_h2, a2s, a2d,
                                           g_ssrc, g_sdst, N_NODES);         // 5
    k_max<<<maxBlk, 256>>>(ei, g_ssrc, g_sdst, g_m2);                        // 6
    k_scat64<<<sc64, 256>>>(ei, g_h2, g_ssrc, g_sdst, g_m2, g_d2, g_acc2);   // 7
    k_fin<OUTD, false><<<fin2Blk, 256>>>(g_acc2, g_d2, b2, out);             // 8
}

// round 9
// speedup vs baseline: 4.7806x; 4.7806x over previous
#include <cuda_runtime.h>
#include <cuda_fp16.h>
#include <math.h>
#include <float.h>

#define N_NODES 100000
#define N_EDGES 1600000
#define ETOT    (N_EDGES + N_NODES)
#define IN_DIM  256
#define HID     128
#define OUTD    64
#define NEG_SLOPE 0.2f
#define SCAN_NB ((N_NODES + 255) / 256)   // 391
#define FULLM 0xffffffffu

// ---------------- scratch (static device globals; no allocation) ----------------
static __device__ __align__(128) float g_h1[(size_t)N_NODES * HID];   // x@W1 (fp32)
static __device__ __align__(128) float g_o1[(size_t)N_NODES * HID];   // elu(agg1 + b1)
static __device__ __align__(128) float g_h2[(size_t)N_NODES * OUTD];  // o1@W2
static __device__ float g_ssrc[N_NODES];
static __device__ float g_sdst[N_NODES];
static __device__ int   g_cnt[N_NODES];
static __device__ int   g_cur[N_NODES];
static __device__ int   g_off[N_NODES + 1];
static __device__ int   g_bsum[512];
static __device__ int   g_col[ETOT];

// ---------------- CSR build (verbatim from the 7409us passing kernel) ----------------
__global__ void k_zeroA() {
    int i = blockIdx.x * blockDim.x + threadIdx.x;
    if (i < N_NODES) g_cnt[i] = 0;
}
__global__ void k_zeroB() {
    int i = blockIdx.x * blockDim.x + threadIdx.x;
    if (i < N_NODES) g_cur[i] = 0;
}

__global__ void k_count(const int* __restrict__ ei) {
    int t = blockIdx.x * blockDim.x + threadIdx.x;
    if (t >= ETOT) return;
    int dst = (t < N_EDGES) ? ei[N_EDGES + t] : (t - N_EDGES);
    atomicAdd(&g_cnt[dst], 1);
}

__global__ void k_scan1() {
    __shared__ int s[256];
    int t = threadIdx.x, idx = blockIdx.x * 256 + t;
    int v = (idx < N_NODES) ? g_cnt[idx] : 0;
    s[t] = v; __syncthreads();
    #pragma unroll
    for (int o = 1; o < 256; o <<= 1) {
        int u = (t >= o) ? s[t - o] : 0;
        __syncthreads();
        s[t] += u;
        __syncthreads();
    }
    if (idx < N_NODES) g_off[idx] = s[t] - v;
    if (t == 255) g_bsum[blockIdx.x] = s[t];
}

__global__ void k_scan2(int nb) {
    __shared__ int s[512];
    int t = threadIdx.x;
    int v = (t < nb) ? g_bsum[t] : 0;
    s[t] = v; __syncthreads();
    #pragma unroll
    for (int o = 1; o < 512; o <<= 1) {
        int u = (t >= o) ? s[t - o] : 0;
        __syncthreads();
        s[t] += u;
        __syncthreads();
    }
    g_bsum[t] = s[t] - v;
}

__global__ void k_scan3() {
    int t = threadIdx.x, idx = blockIdx.x * 256 + t;
    if (idx < N_NODES) g_off[idx] += g_bsum[blockIdx.x];
    if (idx == 0) g_off[N_NODES] = ETOT;
}

__global__ void k_fill(const int* __restrict__ ei) {
    int t = blockIdx.x * blockDim.x + threadIdx.x;
    if (t >= ETOT) return;
    int src, dst;
    if (t < N_EDGES) { src = ei[t]; dst = ei[N_EDGES + t]; }
    else             { src = dst = t - N_EDGES; }
    int pos = g_off[dst] + atomicAdd(&g_cur[dst], 1);
    g_col[pos] = src;
}

// ---------------- GEMM + fused attention-score epilogue (verbatim) ----------------
template<int K, int NCOL, int BM>
__global__ void k_gemm(const float* __restrict__ A, const float* __restrict__ W,
                       float* __restrict__ C,
                       const float* __restrict__ asrc, const float* __restrict__ adst,
                       float* __restrict__ ssrc, float* __restrict__ sdst, int M) {
    constexpr int TN = 4, TM = 8, BK = 16;
    constexpr int TX = NCOL / TN;
    constexpr int ALD = BM + 4;
    constexpr int NC4 = NCOL / 4;
    __shared__ float As[BK][ALD];
    __shared__ float Ws[BK][NCOL];
    const int tid = threadIdx.x;
    const int tx = tid % TX;
    const int ty = tid / TX;
    const int m0 = blockIdx.x * BM;

    float acc[TM][TN];
    #pragma unroll
    for (int r = 0; r < TM; r++)
        #pragma unroll
        for (int n = 0; n < TN; n++) acc[r][n] = 0.f;

    for (int k0 = 0; k0 < K; k0 += BK) {
        #pragma unroll
        for (int i = tid; i < BM * 4; i += 256) {
            int row = i >> 2, kf = (i & 3) * 4;
            float4 v = make_float4(0.f, 0.f, 0.f, 0.f);
            int gr = m0 + row;
            if (gr < M) v = *(const float4*)(A + (size_t)gr * K + k0 + kf);
            As[kf + 0][row] = v.x;
            As[kf + 1][row] = v.y;
            As[kf + 2][row] = v.z;
            As[kf + 3][row] = v.w;
        }
        #pragma unroll
        for (int i = tid; i < BK * NC4; i += 256) {
            int wr = i / NC4, wc = (i % NC4) * 4;
            *(float4*)&Ws[wr][wc] = *(const float4*)(W + (size_t)(k0 + wr) * NCOL + wc);
        }
        __syncthreads();
        #pragma unroll
        for (int kk = 0; kk < BK; kk++) {
            float4 a0 = *(const float4*)&As[kk][ty * TM];
            float4 a1 = *(const float4*)&As[kk][ty * TM + 4];
            float4 wv = *(const float4*)&Ws[kk][tx * TN];
            float a_[TM] = {a0.x, a0.y, a0.z, a0.w, a1.x, a1.y, a1.z, a1.w};
            float w_[TN] = {wv.x, wv.y, wv.z, wv.w};
            #pragma unroll
            for (int r = 0; r < TM; r++)
                #pragma unroll
                for (int n = 0; n < TN; n++)
                    acc[r][n] = fmaf(a_[r], w_[n], acc[r][n]);
        }
        __syncthreads();
    }

    #pragma unroll
    for (int r = 0; r < TM; r++) {
        int row = m0 + ty * TM + r;
        if (row < M) {
            float4 v = make_float4(acc[r][0], acc[r][1], acc[r][2], acc[r][3]);
            *(float4*)(C + (size_t)row * NCOL + tx * TN) = v;
        }
    }

    float4 a1v = *(const float4*)(asrc + tx * TN);
    float4 a2v = *(const float4*)(adst + tx * TN);
    float p1[TM], p2[TM];
    #pragma unroll
    for (int r = 0; r < TM; r++) {
        p1[r] = acc[r][0] * a1v.x + acc[r][1] * a1v.y + acc[r][2] * a1v.z + acc[r][3] * a1v.w;
        p2[r] = acc[r][0] * a2v.x + acc[r][1] * a2v.y + acc[r][2] * a2v.z + acc[r][3] * a2v.w;
    }
    #pragma unroll
    for (int o = TX / 2; o; o >>= 1) {
        #pragma unroll
        for (int r = 0; r < TM; r++) {
            p1[r] += __shfl_xor_sync(FULLM, p1[r], o);
            p2[r] += __shfl_xor_sync(FULLM, p2[r], o);
        }
    }
    if (tx == 0) {
        #pragma unroll
        for (int r = 0; r < TM; r++) {
            int row = m0 + ty * TM + r;
            if (row < M) { ssrc[row] = p1[r]; sdst[row] = p2[r]; }
        }
    }
}

// ---------------- NEW: flat fp32 -> fp16 converter (g_h1 -> d_out) ----------------
__global__ void k_half(const float* __restrict__ src, __half* __restrict__ dst) {
    int i = blockIdx.x * blockDim.x + threadIdx.x;   // over N*HID/4 groups
    if (i >= N_NODES * (HID / 4)) return;
    float4 v = ((const float4*)src)[i];
    __half* p = dst + (size_t)i * 4;
    p[0] = __float2half_rn(v.x);
    p[1] = __float2half_rn(v.y);
    p[2] = __float2half_rn(v.z);
    p[3] = __float2half_rn(v.w);
}

// ---------------- layer-1 agg: R3 online-softmax, h loads switched to fp16 ----------------
__global__ void k_aggH(const __half* __restrict__ h,
                       const float* __restrict__ ssrc, const float* __restrict__ sdst,
                       const float* __restrict__ bias, float* __restrict__ out) {
    int node = (blockIdx.x * blockDim.x + threadIdx.x) >> 5;
    if (node >= N_NODES) return;
    int lane = threadIdx.x & 31;
    int beg = g_off[node], end = g_off[node + 1];
    float sd = sdst[node];

    float m = -FLT_MAX, s = 0.f;
    float acc0 = 0.f, acc1 = 0.f, acc2 = 0.f, acc3 = 0.f;

    for (int c0 = beg; c0 < end; c0 += 32) {
        int n = min(32, end - c0);
        float e = -FLT_MAX; int cs = 0;
        if (lane < n) {
            cs = g_col[c0 + lane];
            float t = ssrc[cs] + sd;
            e = (t > 0.f) ? t : NEG_SLOPE * t;
        }
        float cm = e;
        #pragma unroll
        for (int o = 16; o; o >>= 1) cm = fmaxf(cm, __shfl_xor_sync(FULLM, cm, o));
        float mn = fmaxf(m, cm);
        float scale = __expf(m - mn);
        s *= scale;
        acc0 *= scale; acc1 *= scale; acc2 *= scale; acc3 *= scale;

        float w = (lane < n) ? __expf(e - mn) : 0.f;
        float ws = w;
        #pragma unroll
        for (int o = 16; o; o >>= 1) ws += __shfl_xor_sync(FULLM, ws, o);
        s += ws;
        m = mn;

        int k = 0;
        for (; k + 4 <= n; k += 4) {
            float w0 = __shfl_sync(FULLM, w, k);
            float w1 = __shfl_sync(FULLM, w, k + 1);
            float w2 = __shfl_sync(FULLM, w, k + 2);
            float w3 = __shfl_sync(FULLM, w, k + 3);
            int s0 = __shfl_sync(FULLM, cs, k);
            int s1 = __shfl_sync(FULLM, cs, k + 1);
            int s2 = __shfl_sync(FULLM, cs, k + 2);
            int s3 = __shfl_sync(FULLM, cs, k + 3);
            uint2 r0 = *(const uint2*)(h + (size_t)s0 * HID + lane * 4);
            uint2 r1 = *(const uint2*)(h + (size_t)s1 * HID + lane * 4);
            uint2 r2 = *(const uint2*)(h + (size_t)s2 * HID + lane * 4);
            uint2 r3 = *(const uint2*)(h + (size_t)s3 * HID + lane * 4);
            const __half* p0 = reinterpret_cast<const __half*>(&r0);
            const __half* p1 = reinterpret_cast<const __half*>(&r1);
            const __half* p2 = reinterpret_cast<const __half*>(&r2);
            const __half* p3 = reinterpret_cast<const __half*>(&r3);
            acc0 = fmaf(w0, __half2float(p0[0]), acc0);
            acc1 = fmaf(w0, __half2float(p0[1]), acc1);
            acc2 = fmaf(w0, __half2float(p0[2]), acc2);
            acc3 = fmaf(w0, __half2float(p0[3]), acc3);
            acc0 = fmaf(w1, __half2float(p1[0]), acc0);
            acc1 = fmaf(w1, __half2float(p1[1]), acc1);
            acc2 = fmaf(w1, __half2float(p1[2]), acc2);
            acc3 = fmaf(w1, __half2float(p1[3]), acc3);
            acc0 = fmaf(w2, __half2float(p2[0]), acc0);
            acc1 = fmaf(w2, __half2float(p2[1]), acc1);
            acc2 = fmaf(w2, __half2float(p2[2]), acc2);
            acc3 = fmaf(w2, __half2float(p2[3]), acc3);
            acc0 = fmaf(w3, __half2float(p3[0]), acc0);
            acc1 = fmaf(w3, __half2float(p3[1]), acc1);
            acc2 = fmaf(w3, __half2float(p3[2]), acc2);
            acc3 = fmaf(w3, __half2float(p3[3]), acc3);
        }
        for (; k < n; k++) {
            float w0 = __shfl_sync(FULLM, w, k);
            int s0 = __shfl_sync(FULLM, cs, k);
            uint2 r0 = *(const uint2*)(h + (size_t)s0 * HID + lane * 4);
            const __half* p0 = reinterpret_cast<const __half*>(&r0);
            acc0 = fmaf(w0, __half2float(p0[0]), acc0);
            acc1 = fmaf(w0, __half2float(p0[1]), acc1);
            acc2 = fmaf(w0, __half2float(p0[2]), acc2);
            acc3 = fmaf(w0, __half2float(p0[3]), acc3);
        }
    }

    float inv = 1.f / s;
    float4 bv = *(const float4*)(bias + lane * 4);
    float r0 = acc0 * inv + bv.x;
    float r1 = acc1 * inv + bv.y;
    float r2 = acc2 * inv + bv.z;
    float r3 = acc3 * inv + bv.w;
    r0 = (r0 > 0.f) ? r0 : expm1f(r0);
    r1 = (r1 > 0.f) ? r1 : expm1f(r1);
    r2 = (r2 > 0.f) ? r2 : expm1f(r2);
    r3 = (r3 > 0.f) ? r3 : expm1f(r3);
    float4 o4 = make_float4(r0, r1, r2, r3);
    *(float4*)(out + (size_t)node * HID + lane * 4) = o4;
}

// ---------------- layer-2 agg: verbatim R3 online-softmax (fp32, F=64) ----------------
__global__ void k_agg64(const float* __restrict__ h,
                        const float* __restrict__ ssrc, const float* __restrict__ sdst,
                        const float* __restrict__ bias, float* __restrict__ out) {
    int node = (blockIdx.x * blockDim.x + threadIdx.x) >> 5;
    if (node >= N_NODES) return;
    int lane = threadIdx.x & 31;
    int beg = g_off[node], end = g_off[node + 1];
    float sd = sdst[node];

    float m = -FLT_MAX, s = 0.f;
    float acc0 = 0.f, acc1 = 0.f;

    for (int c0 = beg; c0 < end; c0 += 32) {
        int n = min(32, end - c0);
        float e = -FLT_MAX; int cs = 0;
        if (lane < n) {
            cs = g_col[c0 + lane];
            float t = ssrc[cs] + sd;
            e = (t > 0.f) ? t : NEG_SLOPE * t;
        }
        float cm = e;
        #pragma unroll
        for (int o = 16; o; o >>= 1) cm = fmaxf(cm, __shfl_xor_sync(FULLM, cm, o));
        float mn = fmaxf(m, cm);
        float scale = __expf(m - mn);
        s *= scale;
        acc0 *= scale; acc1 *= scale;

        float w = (lane < n) ? __expf(e - mn) : 0.f;
        float ws = w;
        #pragma unroll
        for (int o = 16; o; o >>= 1) ws += __shfl_xor_sync(FULLM, ws, o);
        s += ws;
        m = mn;

        int k = 0;
        for (; k + 4 <= n; k += 4) {
            float w0 = __shfl_sync(FULLM, w, k);
            float w1 = __shfl_sync(FULLM, w, k + 1);
            float w2 = __shfl_sync(FULLM, w, k + 2);
            float w3 = __shfl_sync(FULLM, w, k + 3);
            int s0 = __shfl_sync(FULLM, cs, k);
            int s1 = __shfl_sync(FULLM, cs, k + 1);
            int s2 = __shfl_sync(FULLM, cs, k + 2);
            int s3 = __shfl_sync(FULLM, cs, k + 3);
            float2 v0 = *(const float2*)(h + (size_t)s0 * OUTD + lane * 2);
            float2 v1 = *(const float2*)(h + (size_t)s1 * OUTD + lane * 2);
            float2 v2 = *(const float2*)(h + (size_t)s2 * OUTD + lane * 2);
            float2 v3 = *(const float2*)(h + (size_t)s3 * OUTD + lane * 2);
            acc0 = fmaf(w0, v0.x, acc0); acc1 = fmaf(w0, v0.y, acc1);
            acc0 = fmaf(w1, v1.x, acc0); acc1 = fmaf(w1, v1.y, acc1);
            acc0 = fmaf(w2, v2.x, acc0); acc1 = fmaf(w2, v2.y, acc1);
            acc0 = fmaf(w3, v3.x, acc0); acc1 = fmaf(w3, v3.y, acc1);
        }
        for (; k < n; k++) {
            float w0 = __shfl_sync(FULLM, w, k);
            int s0 = __shfl_sync(FULLM, cs, k);
            float2 v0 = *(const float2*)(h + (size_t)s0 * OUTD + lane * 2);
            acc0 = fmaf(w0, v0.x, acc0); acc1 = fmaf(w0, v0.y, acc1);
        }
    }

    float inv = 1.f / s;
    float2 bv = *(const float2*)(bias + lane * 2);
    float2 o2 = make_float2(acc0 * inv + bv.x, acc1 * inv + bv.y);
    *(float2*)(out + (size_t)node * OUTD + lane * 2) = o2;
}

// ---------------- launch ----------------
extern "C" void kernel_launch(void* const* d_in, const int* in_sizes, int n_in,
                              void* d_out, int out_size) {
    const float* x   = (const float*)d_in[0];
    const int*   ei  = (const int*)d_in[1];
    const float* W1  = (const float*)d_in[2];
    const float* a1s = (const float*)d_in[3];
    const float* a1d = (const float*)d_in[4];
    const float* b1  = (const float*)d_in[5];
    const float* W2  = (const float*)d_in[6];
    const float* a2s = (const float*)d_in[7];
    const float* a2d = (const float*)d_in[8];
    const float* b2  = (const float*)d_in[9];

    // d_out (device, 25.6 MB): phase 1 holds h1 as fp16 [N,128] (exactly 25.6 MB);
    // phase 2 it is fully overwritten with the final fp32 output [N,64] by k_agg64.
    __half* h1h = (__half*)d_out;
    float*  out = (float*)d_out;

    const int nodeBlk = (N_NODES + 255) / 256;
    const int edgeBlk = (ETOT + 255) / 256;
    const int warpBlk = (N_NODES * 32 + 255) / 256;
    const int g1Blk   = (N_NODES + 63) / 64;     // BM=64
    const int g2Blk   = (N_NODES + 127) / 128;   // BM=128
    const int cvBlk   = (N_NODES * (HID / 4) + 255) / 256;

    k_zeroA<<<nodeBlk, 256>>>();                                             // 0
    k_count<<<edgeBlk, 256>>>(ei);                                           // 1
    k_gemm<IN_DIM, HID, 64><<<g1Blk, 256>>>(x, W1, g_h1, a1s, a1d,
                                            g_ssrc, g_sdst, N_NODES);        // 2
    k_half<<<cvBlk, 256>>>(g_h1, h1h);                                       // 3 <- ncu
    k_zeroB<<<nodeBlk, 256>>>();                                             // 4
    k_scan1<<<SCAN_NB, 256>>>();                                             // 5
    k_scan2<<<1, 512>>>(SCAN_NB);                                            // 6
    k_scan3<<<SCAN_NB, 256>>>();                                             // 7
    k_fill<<<edgeBlk, 256>>>(ei);                                            // 8
    k_aggH<<<warpBlk, 256>>>(h1h, g_ssrc, g_sdst, b1, g_o1);                 // 9
    k_gemm<HID, OUTD, 128><<<g2Blk, 256>>>(g_o1, W2, g_h2, a2s, a2d,
                                           g_ssrc, g_sdst, N_NODES);         // 10
    k_agg64<<<warpBlk, 256>>>(g_h2, g_ssrc, g_sdst, b2, out);                // 11
}

// round 10
// speedup vs baseline: 10.3995x; 2.1753x over previous
#include <cuda_runtime.h>
#include <cuda_fp16.h>
#include <math.h>
#include <float.h>

#define N_NODES 100000
#define N_EDGES 1600000
#define ETOT    (N_EDGES + N_NODES)
#define IN_DIM  256
#define HID     128
#define OUTD    64
#define NEG_SLOPE 0.2f
#define SCAN_NB ((N_NODES + 255) / 256)   // 391
#define FULLM 0xffffffffu

// ---------------- scratch (static device globals; no allocation) ----------------
// Empirical placement law (R4/R9 timing experiments): random gathers from
// statics run at ~200 GB/s; streams are fast. Gather tables (h1 fp16, h2 fp32)
// therefore live in d_out (device). Statics are stream/tiny-access only.
static __device__ __align__(128) float g_h1[(size_t)N_NODES * HID];   // x@W1 (fp32, streamed)
static __device__ __align__(128) float g_o1[(size_t)N_NODES * HID];   // elu(agg1 + b1) (streamed)
static __device__ __align__(128) float g_o2[(size_t)N_NODES * OUTD];  // staged final (streamed)
static __device__ float g_ssrc[N_NODES];
static __device__ float g_sdst[N_NODES];
static __device__ int   g_cnt[N_NODES];
static __device__ int   g_cur[N_NODES];
static __device__ int   g_off[N_NODES + 1];
static __device__ int   g_bsum[512];
static __device__ int   g_col[ETOT];

// ---------------- CSR build (verbatim from verified kernel) ----------------
__global__ void k_zeroA() {
    int i = blockIdx.x * blockDim.x + threadIdx.x;
    if (i < N_NODES) g_cnt[i] = 0;
}
__global__ void k_zeroB() {
    int i = blockIdx.x * blockDim.x + threadIdx.x;
    if (i < N_NODES) g_cur[i] = 0;
}

__global__ void k_count(const int* __restrict__ ei) {
    int t = blockIdx.x * blockDim.x + threadIdx.x;
    if (t >= ETOT) return;
    int dst = (t < N_EDGES) ? ei[N_EDGES + t] : (t - N_EDGES);
    atomicAdd(&g_cnt[dst], 1);
}

__global__ void k_scan1() {
    __shared__ int s[256];
    int t = threadIdx.x, idx = blockIdx.x * 256 + t;
    int v = (idx < N_NODES) ? g_cnt[idx] : 0;
    s[t] = v; __syncthreads();
    #pragma unroll
    for (int o = 1; o < 256; o <<= 1) {
        int u = (t >= o) ? s[t - o] : 0;
        __syncthreads();
        s[t] += u;
        __syncthreads();
    }
    if (idx < N_NODES) g_off[idx] = s[t] - v;
    if (t == 255) g_bsum[blockIdx.x] = s[t];
}

__global__ void k_scan2(int nb) {
    __shared__ int s[512];
    int t = threadIdx.x;
    int v = (t < nb) ? g_bsum[t] : 0;
    s[t] = v; __syncthreads();
    #pragma unroll
    for (int o = 1; o < 512; o <<= 1) {
        int u = (t >= o) ? s[t - o] : 0;
        __syncthreads();
        s[t] += u;
        __syncthreads();
    }
    g_bsum[t] = s[t] - v;
}

__global__ void k_scan3() {
    int t = threadIdx.x, idx = blockIdx.x * 256 + t;
    if (idx < N_NODES) g_off[idx] += g_bsum[blockIdx.x];
    if (idx == 0) g_off[N_NODES] = ETOT;
}

__global__ void k_fill(const int* __restrict__ ei) {
    int t = blockIdx.x * blockDim.x + threadIdx.x;
    if (t >= ETOT) return;
    int src, dst;
    if (t < N_EDGES) { src = ei[t]; dst = ei[N_EDGES + t]; }
    else             { src = dst = t - N_EDGES; }
    int pos = g_off[dst] + atomicAdd(&g_cur[dst], 1);
    g_col[pos] = src;
}

// ---------------- GEMM + fused attention-score epilogue (verbatim) ----------------
template<int K, int NCOL, int BM>
__global__ void k_gemm(const float* __restrict__ A, const float* __restrict__ W,
                       float* __restrict__ C,
                       const float* __restrict__ asrc, const float* __restrict__ adst,
                       float* __restrict__ ssrc, float* __restrict__ sdst, int M) {
    constexpr int TN = 4, TM = 8, BK = 16;
    constexpr int TX = NCOL / TN;
    constexpr int ALD = BM + 4;
    constexpr int NC4 = NCOL / 4;
    __shared__ float As[BK][ALD];
    __shared__ float Ws[BK][NCOL];
    const int tid = threadIdx.x;
    const int tx = tid % TX;
    const int ty = tid / TX;
    const int m0 = blockIdx.x * BM;

    float acc[TM][TN];
    #pragma unroll
    for (int r = 0; r < TM; r++)
        #pragma unroll
        for (int n = 0; n < TN; n++) acc[r][n] = 0.f;

    for (int k0 = 0; k0 < K; k0 += BK) {
        #pragma unroll
        for (int i = tid; i < BM * 4; i += 256) {
            int row = i >> 2, kf = (i & 3) * 4;
            float4 v = make_float4(0.f, 0.f, 0.f, 0.f);
            int gr = m0 + row;
            if (gr < M) v = *(const float4*)(A + (size_t)gr * K + k0 + kf);
            As[kf + 0][row] = v.x;
            As[kf + 1][row] = v.y;
            As[kf + 2][row] = v.z;
            As[kf + 3][row] = v.w;
        }
        #pragma unroll
        for (int i = tid; i < BK * NC4; i += 256) {
            int wr = i / NC4, wc = (i % NC4) * 4;
            *(float4*)&Ws[wr][wc] = *(const float4*)(W + (size_t)(k0 + wr) * NCOL + wc);
        }
        __syncthreads();
        #pragma unroll
        for (int kk = 0; kk < BK; kk++) {
            float4 a0 = *(const float4*)&As[kk][ty * TM];
            float4 a1 = *(const float4*)&As[kk][ty * TM + 4];
            float4 wv = *(const float4*)&Ws[kk][tx * TN];
            float a_[TM] = {a0.x, a0.y, a0.z, a0.w, a1.x, a1.y, a1.z, a1.w};
            float w_[TN] = {wv.x, wv.y, wv.z, wv.w};
            #pragma unroll
            for (int r = 0; r < TM; r++)
                #pragma unroll
                for (int n = 0; n < TN; n++)
                    acc[r][n] = fmaf(a_[r], w_[n], acc[r][n]);
        }
        __syncthreads();
    }

    #pragma unroll
    for (int r = 0; r < TM; r++) {
        int row = m0 + ty * TM + r;
        if (row < M) {
            float4 v = make_float4(acc[r][0], acc[r][1], acc[r][2], acc[r][3]);
            *(float4*)(C + (size_t)row * NCOL + tx * TN) = v;
        }
    }

    float4 a1v = *(const float4*)(asrc + tx * TN);
    float4 a2v = *(const float4*)(adst + tx * TN);
    float p1[TM], p2[TM];
    #pragma unroll
    for (int r = 0; r < TM; r++) {
        p1[r] = acc[r][0] * a1v.x + acc[r][1] * a1v.y + acc[r][2] * a1v.z + acc[r][3] * a1v.w;
        p2[r] = acc[r][0] * a2v.x + acc[r][1] * a2v.y + acc[r][2] * a2v.z + acc[r][3] * a2v.w;
    }
    #pragma unroll
    for (int o = TX / 2; o; o >>= 1) {
        #pragma unroll
        for (int r = 0; r < TM; r++) {
            p1[r] += __shfl_xor_sync(FULLM, p1[r], o);
            p2[r] += __shfl_xor_sync(FULLM, p2[r], o);
        }
    }
    if (tx == 0) {
        #pragma unroll
        for (int r = 0; r < TM; r++) {
            int row = m0 + ty * TM + r;
            if (row < M) { ssrc[row] = p1[r]; sdst[row] = p2[r]; }
        }
    }
}

// ---------------- flat fp32 -> fp16 converter (g_h1 -> d_out) ----------------
__global__ void k_half(const float* __restrict__ src, __half* __restrict__ dst) {
    int i = blockIdx.x * blockDim.x + threadIdx.x;   // over N*HID/4 groups
    if (i >= N_NODES * (HID / 4)) return;
    float4 v = ((const float4*)src)[i];
    __half* p = dst + (size_t)i * 4;
    p[0] = __float2half_rn(v.x);
    p[1] = __float2half_rn(v.y);
    p[2] = __float2half_rn(v.z);
    p[3] = __float2half_rn(v.w);
}

// ---------------- layer-1 agg: online-softmax, fp16 h gathers (verbatim R9) ----------------
__global__ void k_aggH(const __half* __restrict__ h,
                       const float* __restrict__ ssrc, const float* __restrict__ sdst,
                       const float* __restrict__ bias, float* __restrict__ out) {
    int node = (blockIdx.x * blockDim.x + threadIdx.x) >> 5;
    if (node >= N_NODES) return;
    int lane = threadIdx.x & 31;
    int beg = g_off[node], end = g_off[node + 1];
    float sd = sdst[node];

    float m = -FLT_MAX, s = 0.f;
    float acc0 = 0.f, acc1 = 0.f, acc2 = 0.f, acc3 = 0.f;

    for (int c0 = beg; c0 < end; c0 += 32) {
        int n = min(32, end - c0);
        float e = -FLT_MAX; int cs = 0;
        if (lane < n) {
            cs = g_col[c0 + lane];
            float t = ssrc[cs] + sd;
            e = (t > 0.f) ? t : NEG_SLOPE * t;
        }
        float cm = e;
        #pragma unroll
        for (int o = 16; o; o >>= 1) cm = fmaxf(cm, __shfl_xor_sync(FULLM, cm, o));
        float mn = fmaxf(m, cm);
        float scale = __expf(m - mn);
        s *= scale;
        acc0 *= scale; acc1 *= scale; acc2 *= scale; acc3 *= scale;

        float w = (lane < n) ? __expf(e - mn) : 0.f;
        float ws = w;
        #pragma unroll
        for (int o = 16; o; o >>= 1) ws += __shfl_xor_sync(FULLM, ws, o);
        s += ws;
        m = mn;

        int k = 0;
        for (; k + 4 <= n; k += 4) {
            float w0 = __shfl_sync(FULLM, w, k);
            float w1 = __shfl_sync(FULLM, w, k + 1);
            float w2 = __shfl_sync(FULLM, w, k + 2);
            float w3 = __shfl_sync(FULLM, w, k + 3);
            int s0 = __shfl_sync(FULLM, cs, k);
            int s1 = __shfl_sync(FULLM, cs, k + 1);
            int s2 = __shfl_sync(FULLM, cs, k + 2);
            int s3 = __shfl_sync(FULLM, cs, k + 3);
            uint2 r0 = *(const uint2*)(h + (size_t)s0 * HID + lane * 4);
            uint2 r1 = *(const uint2*)(h + (size_t)s1 * HID + lane * 4);
            uint2 r2 = *(const uint2*)(h + (size_t)s2 * HID + lane * 4);
            uint2 r3 = *(const uint2*)(h + (size_t)s3 * HID + lane * 4);
            const __half* p0 = reinterpret_cast<const __half*>(&r0);
            const __half* p1 = reinterpret_cast<const __half*>(&r1);
            const __half* p2 = reinterpret_cast<const __half*>(&r2);
            const __half* p3 = reinterpret_cast<const __half*>(&r3);
            acc0 = fmaf(w0, __half2float(p0[0]), acc0);
            acc1 = fmaf(w0, __half2float(p0[1]), acc1);
            acc2 = fmaf(w0, __half2float(p0[2]), acc2);
            acc3 = fmaf(w0, __half2float(p0[3]), acc3);
            acc0 = fmaf(w1, __half2float(p1[0]), acc0);
            acc1 = fmaf(w1, __half2float(p1[1]), acc1);
            acc2 = fmaf(w1, __half2float(p1[2]), acc2);
            acc3 = fmaf(w1, __half2float(p1[3]), acc3);
            acc0 = fmaf(w2, __half2float(p2[0]), acc0);
            acc1 = fmaf(w2, __half2float(p2[1]), acc1);
            acc2 = fmaf(w2, __half2float(p2[2]), acc2);
            acc3 = fmaf(w2, __half2float(p2[3]), acc3);
            acc0 = fmaf(w3, __half2float(p3[0]), acc0);
            acc1 = fmaf(w3, __half2float(p3[1]), acc1);
            acc2 = fmaf(w3, __half2float(p3[2]), acc2);
            acc3 = fmaf(w3, __half2float(p3[3]), acc3);
        }
        for (; k < n; k++) {
            float w0 = __shfl_sync(FULLM, w, k);
            int s0 = __shfl_sync(FULLM, cs, k);
            uint2 r0 = *(const uint2*)(h + (size_t)s0 * HID + lane * 4);
            const __half* p0 = reinterpret_cast<const __half*>(&r0);
            acc0 = fmaf(w0, __half2float(p0[0]), acc0);
            acc1 = fmaf(w0, __half2float(p0[1]), acc1);
            acc2 = fmaf(w0, __half2float(p0[2]), acc2);
            acc3 = fmaf(w0, __half2float(p0[3]), acc3);
        }
    }

    float inv = 1.f / s;
    float4 bv = *(const float4*)(bias + lane * 4);
    float r0 = acc0 * inv + bv.x;
    float r1 = acc1 * inv + bv.y;
    float r2 = acc2 * inv + bv.z;
    float r3 = acc3 * inv + bv.w;
    r0 = (r0 > 0.f) ? r0 : expm1f(r0);
    r1 = (r1 > 0.f) ? r1 : expm1f(r1);
    r2 = (r2 > 0.f) ? r2 : expm1f(r2);
    r3 = (r3 > 0.f) ? r3 : expm1f(r3);
    float4 o4 = make_float4(r0, r1, r2, r3);
    *(float4*)(out + (size_t)node * HID + lane * 4) = o4;
}

// ---------------- layer-2 agg: verbatim online-softmax (fp32, F=64) ----------------
__global__ void k_agg64(const float* __restrict__ h,
                        const float* __restrict__ ssrc, const float* __restrict__ sdst,
                        const float* __restrict__ bias, float* __restrict__ out) {
    int node = (blockIdx.x * blockDim.x + threadIdx.x) >> 5;
    if (node >= N_NODES) return;
    int lane = threadIdx.x & 31;
    int beg = g_off[node], end = g_off[node + 1];
    float sd = sdst[node];

    float m = -FLT_MAX, s = 0.f;
    float acc0 = 0.f, acc1 = 0.f;

    for (int c0 = beg; c0 < end; c0 += 32) {
        int n = min(32, end - c0);
        float e = -FLT_MAX; int cs = 0;
        if (lane < n) {
            cs = g_col[c0 + lane];
            float t = ssrc[cs] + sd;
            e = (t > 0.f) ? t : NEG_SLOPE * t;
        }
        float cm = e;
        #pragma unroll
        for (int o = 16; o; o >>= 1) cm = fmaxf(cm, __shfl_xor_sync(FULLM, cm, o));
        float mn = fmaxf(m, cm);
        float scale = __expf(m - mn);
        s *= scale;
        acc0 *= scale; acc1 *= scale;

        float w = (lane < n) ? __expf(e - mn) : 0.f;
        float ws = w;
        #pragma unroll
        for (int o = 16; o; o >>= 1) ws += __shfl_xor_sync(FULLM, ws, o);
        s += ws;
        m = mn;

        int k = 0;
        for (; k + 4 <= n; k += 4) {
            float w0 = __shfl_sync(FULLM, w, k);
            float w1 = __shfl_sync(FULLM, w, k + 1);
            float w2 = __shfl_sync(FULLM, w, k + 2);
            float w3 = __shfl_sync(FULLM, w, k + 3);
            int s0 = __shfl_sync(FULLM, cs, k);
            int s1 = __shfl_sync(FULLM, cs, k + 1);
            int s2 = __shfl_sync(FULLM, cs, k + 2);
            int s3 = __shfl_sync(FULLM, cs, k + 3);
            float2 v0 = *(const float2*)(h + (size_t)s0 * OUTD + lane * 2);
            float2 v1 = *(const float2*)(h + (size_t)s1 * OUTD + lane * 2);
            float2 v2 = *(const float2*)(h + (size_t)s2 * OUTD + lane * 2);
            float2 v3 = *(const float2*)(h + (size_t)s3 * OUTD + lane * 2);
            acc0 = fmaf(w0, v0.x, acc0); acc1 = fmaf(w0, v0.y, acc1);
            acc0 = fmaf(w1, v1.x, acc0); acc1 = fmaf(w1, v1.y, acc1);
            acc0 = fmaf(w2, v2.x, acc0); acc1 = fmaf(w2, v2.y, acc1);
            acc0 = fmaf(w3, v3.x, acc0); acc1 = fmaf(w3, v3.y, acc1);
        }
        for (; k < n; k++) {
            float w0 = __shfl_sync(FULLM, w, k);
            int s0 = __shfl_sync(FULLM, cs, k);
            float2 v0 = *(const float2*)(h + (size_t)s0 * OUTD + lane * 2);
            acc0 = fmaf(w0, v0.x, acc0); acc1 = fmaf(w0, v0.y, acc1);
        }
    }

    float inv = 1.f / s;
    float2 bv = *(const float2*)(bias + lane * 2);
    float2 o2 = make_float2(acc0 * inv + bv.x, acc1 * inv + bv.y);
    *(float2*)(out + (size_t)node * OUTD + lane * 2) = o2;
}

// ---------------- final copy (staged result -> d_out), streaming ----------------
__global__ void k_copy(const float* __restrict__ src, float* __restrict__ dst) {
    int i = blockIdx.x * blockDim.x + threadIdx.x;
    if (i < N_NODES * (OUTD / 4)) ((float4*)dst)[i] = ((const float4*)src)[i];
}

// ---------------- launch ----------------
extern "C" void kernel_launch(void* const* d_in, const int* in_sizes, int n_in,
                              void* d_out, int out_size) {
    const float* x   = (const float*)d_in[0];
    const int*   ei  = (const int*)d_in[1];
    const float* W1  = (const float*)d_in[2];
    const float* a1s = (const float*)d_in[3];
    const float* a1d = (const float*)d_in[4];
    const float* b1  = (const float*)d_in[5];
    const float* W2  = (const float*)d_in[6];
    const float* a2s = (const float*)d_in[7];
    const float* a2d = (const float*)d_in[8];
    const float* b2  = (const float*)d_in[9];

    // d_out (device, 25.6 MB), three sequential phases:
    //   1: h1 fp16 [N,128] (25.6 MB) — written by k_half, gathered by k_aggH
    //   2: h2 fp32 [N,64]  (25.6 MB) — written by gemm2, gathered by k_agg64
    //   3: final output fp32         — written by k_copy
    __half* h1h = (__half*)d_out;
    float*  h2  = (float*)d_out;
    float*  out = (float*)d_out;

    const int nodeBlk = (N_NODES + 255) / 256;
    const int edgeBlk = (ETOT + 255) / 256;
    const int warpBlk = (N_NODES * 32 + 255) / 256;
    const int g1Blk   = (N_NODES + 63) / 64;     // BM=64
    const int g2Blk   = (N_NODES + 127) / 128;   // BM=128
    const int cvBlk   = (N_NODES * (HID / 4) + 255) / 256;
    const int cpBlk   = (N_NODES * (OUTD / 4) + 255) / 256;

    k_zeroA<<<nodeBlk, 256>>>();                                             // 0
    k_count<<<edgeBlk, 256>>>(ei);                                           // 1
    k_zeroB<<<nodeBlk, 256>>>();                                             // 2
    k_gemm<IN_DIM, HID, 64><<<g1Blk, 256>>>(x, W1, g_h1, a1s, a1d,
                                            g_ssrc, g_sdst, N_NODES);        // 3 <- ncu
    k_half<<<cvBlk, 256>>>(g_h1, h1h);                                       // 4
    k_scan1<<<SCAN_NB, 256>>>();                                             // 5
    k_scan2<<<1, 512>>>(SCAN_NB);                                            // 6
    k_scan3<<<SCAN_NB, 256>>>();                                             // 7
    k_fill<<<edgeBlk, 256>>>(ei);                                            // 8
    k_aggH<<<warpBlk, 256>>>(h1h, g_ssrc, g_sdst, b1, g_o1);                 // 9
    k_gemm<HID, OUTD, 128><<<g2Blk, 256>>>(g_o1, W2, h2, a2s, a2d,
                                           g_ssrc, g_sdst, N_NODES);         // 10
    k_agg64<<<warpBlk, 256>>>(h2, g_ssrc, g_sdst, b2, g_o2);                 // 11
    k_copy<<<cpBlk, 256>>>(g_o2, out);                                       // 12
}

// round 11
// speedup vs baseline: 14.4272x; 1.3873x over previous
#include <cuda_runtime.h>
#include <cuda_fp16.h>
#include <math.h>
#include <float.h>

#define N_NODES 100000
#define N_EDGES 1600000
#define ETOT    (N_EDGES + N_NODES)
#define IN_DIM  256
#define HID     128
#define OUTD    64
#define NEG_SLOPE 0.2f
#define SCAN_NB ((N_NODES + 255) / 256)   // 391
#define FULLM 0xffffffffu

// ---------------- scratch (static device globals; no allocation) ----------------
// Placement law (measured R4/R9/R10): random gathers from statics ~200 GB/s;
// gathers from d_out are device-fast; streams are fast everywhere.
// Gather tables (h1 fp16, h2 fp32) live in d_out. Statics are stream-only.
static __device__ __align__(128) float g_o1[(size_t)N_NODES * HID];   // elu(agg1+b1), streamed
static __device__ __align__(128) float g_o2[(size_t)N_NODES * OUTD];  // staged final, streamed
static __device__ float g_ssrc[N_NODES];
static __device__ float g_sdst[N_NODES];
static __device__ int   g_cnt[N_NODES];
static __device__ int   g_cur[N_NODES];
static __device__ int   g_off[N_NODES + 1];
static __device__ int   g_bsum[512];
static __device__ int   g_col[ETOT];

// ---------------- CSR build (verbatim, verified) ----------------
__global__ void k_zeroA() {
    int i = blockIdx.x * blockDim.x + threadIdx.x;
    if (i < N_NODES) g_cnt[i] = 0;
}
__global__ void k_zeroB() {
    int i = blockIdx.x * blockDim.x + threadIdx.x;
    if (i < N_NODES) g_cur[i] = 0;
}

__global__ void k_count(const int* __restrict__ ei) {
    int t = blockIdx.x * blockDim.x + threadIdx.x;
    if (t >= ETOT) return;
    int dst = (t < N_EDGES) ? ei[N_EDGES + t] : (t - N_EDGES);
    atomicAdd(&g_cnt[dst], 1);
}

__global__ void k_scan1() {
    __shared__ int s[256];
    int t = threadIdx.x, idx = blockIdx.x * 256 + t;
    int v = (idx < N_NODES) ? g_cnt[idx] : 0;
    s[t] = v; __syncthreads();
    #pragma unroll
    for (int o = 1; o < 256; o <<= 1) {
        int u = (t >= o) ? s[t - o] : 0;
        __syncthreads();
        s[t] += u;
        __syncthreads();
    }
    if (idx < N_NODES) g_off[idx] = s[t] - v;
    if (t == 255) g_bsum[blockIdx.x] = s[t];
}

__global__ void k_scan2(int nb) {
    __shared__ int s[512];
    int t = threadIdx.x;
    int v = (t < nb) ? g_bsum[t] : 0;
    s[t] = v; __syncthreads();
    #pragma unroll
    for (int o = 1; o < 512; o <<= 1) {
        int u = (t >= o) ? s[t - o] : 0;
        __syncthreads();
        s[t] += u;
        __syncthreads();
    }
    g_bsum[t] = s[t] - v;
}

__global__ void k_scan3() {
    int t = threadIdx.x, idx = blockIdx.x * 256 + t;
    if (idx < N_NODES) g_off[idx] += g_bsum[blockIdx.x];
    if (idx == 0) g_off[N_NODES] = ETOT;
}

__global__ void k_fill(const int* __restrict__ ei) {
    int t = blockIdx.x * blockDim.x + threadIdx.x;
    if (t >= ETOT) return;
    int src, dst;
    if (t < N_EDGES) { src = ei[t]; dst = ei[N_EDGES + t]; }
    else             { src = dst = t - N_EDGES; }
    int pos = g_off[dst] + atomicAdd(&g_cur[dst], 1);
    g_col[pos] = src;
}

// ---------------- NEW: tensor-core GEMM1 (fp16 in, fp32 acc) ----------------
// C[M,128] = x[M,256] @ W1[256,128]; h1 written as fp16 directly to d_out;
// fused ssrc/sdst epilogue from the staged fp32->fp16 tile.
// BM=64, BN=128 (full), k-step 16. 256 threads = 8 warps in 2(m) x 4(n).
__global__ void __launch_bounds__(256) k_gemm1_mma(
        const float* __restrict__ A, const float* __restrict__ W,
        __half* __restrict__ Hout,
        const float* __restrict__ asrc, const float* __restrict__ adst,
        float* __restrict__ ssrc, float* __restrict__ sdst, int M) {
    constexpr int BM = 64;
    __shared__ __half As[BM][24];      // [m][k] pad->24 halves (48B rows)
    __shared__ __half Bs[128][20];     // [n][k] transposed, pad->20 halves (40B rows)
    __shared__ __half Hs[BM][136];     // staged h1 tile, pad->136 (272B rows)

    const int tid = threadIdx.x;
    const int w   = tid >> 5;
    const int lane = tid & 31;
    const int g = lane >> 2;           // 0..7
    const int t = lane & 3;            // 0..3
    const int wm = (w & 1) * 32;       // warp m offset
    const int wn = (w >> 1) * 32;      // warp n offset
    const int m0 = blockIdx.x * BM;

    float c[2][4][4];                  // [m-frag][n-frag][c-reg]
    #pragma unroll
    for (int mf = 0; mf < 2; mf++)
        #pragma unroll
        for (int nf = 0; nf < 4; nf++)
            #pragma unroll
            for (int q = 0; q < 4; q++) c[mf][nf][q] = 0.f;

    const int arow = tid >> 2;         // 0..63
    const int ac4  = (tid & 3) * 4;    // 0,4,8,12

    for (int k0 = 0; k0 < IN_DIM; k0 += 16) {
        // A tile: 64x16 fp32 -> fp16
        {
            float4 v = make_float4(0.f, 0.f, 0.f, 0.f);
            int gr = m0 + arow;
            if (gr < M) v = *(const float4*)(A + (size_t)gr * IN_DIM + k0 + ac4);
            __half2 h01 = __floats2half2_rn(v.x, v.y);
            __half2 h23 = __floats2half2_rn(v.z, v.w);
            *(__half2*)&As[arow][ac4]     = h01;
            *(__half2*)&As[arow][ac4 + 2] = h23;
        }
        // B tile: W[k0..k0+16][0..128] fp32 -> Bs[n][k] fp16 (transposed)
        #pragma unroll
        for (int i = tid; i < 16 * 32; i += 256) {
            int kk = i >> 5;
            int n4 = (i & 31) * 4;
            float4 wv = *(const float4*)(W + (size_t)(k0 + kk) * HID + n4);
            Bs[n4 + 0][kk] = __float2half_rn(wv.x);
            Bs[n4 + 1][kk] = __float2half_rn(wv.y);
            Bs[n4 + 2][kk] = __float2half_rn(wv.z);
            Bs[n4 + 3][kk] = __float2half_rn(wv.w);
        }
        __syncthreads();

        // fragments + mma
        unsigned a[2][4];
        #pragma unroll
        for (int mf = 0; mf < 2; mf++) {
            int r = wm + mf * 16;
            a[mf][0] = *(const unsigned*)&As[r + g][2 * t];
            a[mf][1] = *(const unsigned*)&As[r + 8 + g][2 * t];
            a[mf][2] = *(const unsigned*)&As[r + g][2 * t + 8];
            a[mf][3] = *(const unsigned*)&As[r + 8 + g][2 * t + 8];
        }
        #pragma unroll
        for (int nf = 0; nf < 4; nf++) {
            int n = wn + nf * 8;
            unsigned b0 = *(const unsigned*)&Bs[n + g][2 * t];
            unsigned b1 = *(const unsigned*)&Bs[n + g][2 * t + 8];
            #pragma unroll
            for (int mf = 0; mf < 2; mf++) {
                asm volatile(
                    "mma.sync.aligned.m16n8k16.row.col.f32.f16.f16.f32 "
                    "{%0,%1,%2,%3}, {%4,%5,%6,%7}, {%8,%9}, {%0,%1,%2,%3};"
                    : "+f"(c[mf][nf][0]), "+f"(c[mf][nf][1]),
                      "+f"(c[mf][nf][2]), "+f"(c[mf][nf][3])
                    : "r"(a[mf][0]), "r"(a[mf][1]), "r"(a[mf][2]), "r"(a[mf][3]),
                      "r"(b0), "r"(b1));
            }
        }
        __syncthreads();
    }

    // stage fp32 accums as fp16 into Hs
    #pragma unroll
    for (int mf = 0; mf < 2; mf++) {
        #pragma unroll
        for (int nf = 0; nf < 4; nf++) {
            int r0 = wm + mf * 16 + g;
            int cc = wn + nf * 8 + 2 * t;
            *(__half2*)&Hs[r0][cc]     = __floats2half2_rn(c[mf][nf][0], c[mf][nf][1]);
            *(__half2*)&Hs[r0 + 8][cc] = __floats2half2_rn(c[mf][nf][2], c[mf][nf][3]);
        }
    }
    __syncthreads();

    // h1 store: 64 rows x 128 halves, coalesced uint4
    #pragma unroll
    for (int i = tid; i < 64 * 16; i += 256) {
        int row = i >> 4, seg = i & 15;
        if (m0 + row < M) {
            uint4 v = *(const uint4*)&Hs[row][seg * 8];
            *(uint4*)(Hout + (size_t)(m0 + row) * HID + seg * 8) = v;
        }
    }

    // fused scores: warp w handles rows w*8 .. w*8+7
    float4 a1v = *(const float4*)(asrc + lane * 4);
    float4 a2v = *(const float4*)(adst + lane * 4);
    #pragma unroll
    for (int r = 0; r < 8; r++) {
        int row = w * 8 + r;
        uint2 hv = *(const uint2*)&Hs[row][lane * 4];
        const __half* hp = reinterpret_cast<const __half*>(&hv);
        float f0 = __half2float(hp[0]), f1 = __half2float(hp[1]);
        float f2 = __half2float(hp[2]), f3 = __half2float(hp[3]);
        float d1 = f0 * a1v.x + f1 * a1v.y + f2 * a1v.z + f3 * a1v.w;
        float d2 = f0 * a2v.x + f1 * a2v.y + f2 * a2v.z + f3 * a2v.w;
        #pragma unroll
        for (int o = 16; o; o >>= 1) {
            d1 += __shfl_xor_sync(FULLM, d1, o);
            d2 += __shfl_xor_sync(FULLM, d2, o);
        }
        if (lane == 0 && m0 + row < M) {
            ssrc[m0 + row] = d1;
            sdst[m0 + row] = d2;
        }
    }
}

// ---------------- fp32 GEMM + fused score epilogue (verbatim; used for layer 2) ----------------
template<int K, int NCOL, int BM>
__global__ void k_gemm(const float* __restrict__ A, const float* __restrict__ W,
                       float* __restrict__ C,
                       const float* __restrict__ asrc, const float* __restrict__ adst,
                       float* __restrict__ ssrc, float* __restrict__ sdst, int M) {
    constexpr int TN = 4, TM = 8, BK = 16;
    constexpr int TX = NCOL / TN;
    constexpr int ALD = BM + 4;
    constexpr int NC4 = NCOL / 4;
    __shared__ float As[BK][ALD];
    __shared__ float Ws[BK][NCOL];
    const int tid = threadIdx.x;
    const int tx = tid % TX;
    const int ty = tid / TX;
    const int m0 = blockIdx.x * BM;

    float acc[TM][TN];
    #pragma unroll
    for (int r = 0; r < TM; r++)
        #pragma unroll
        for (int n = 0; n < TN; n++) acc[r][n] = 0.f;

    for (int k0 = 0; k0 < K; k0 += BK) {
        #pragma unroll
        for (int i = tid; i < BM * 4; i += 256) {
            int row = i >> 2, kf = (i & 3) * 4;
            float4 v = make_float4(0.f, 0.f, 0.f, 0.f);
            int gr = m0 + row;
            if (gr < M) v = *(const float4*)(A + (size_t)gr * K + k0 + kf);
            As[kf + 0][row] = v.x;
            As[kf + 1][row] = v.y;
            As[kf + 2][row] = v.z;
            As[kf + 3][row] = v.w;
        }
        #pragma unroll
        for (int i = tid; i < BK * NC4; i += 256) {
            int wr = i / NC4, wc = (i % NC4) * 4;
            *(float4*)&Ws[wr][wc] = *(const float4*)(W + (size_t)(k0 + wr) * NCOL + wc);
        }
        __syncthreads();
        #pragma unroll
        for (int kk = 0; kk < BK; kk++) {
            float4 a0 = *(const float4*)&As[kk][ty * TM];
            float4 a1 = *(const float4*)&As[kk][ty * TM + 4];
            float4 wv = *(const float4*)&Ws[kk][tx * TN];
            float a_[TM] = {a0.x, a0.y, a0.z, a0.w, a1.x, a1.y, a1.z, a1.w};
            float w_[TN] = {wv.x, wv.y, wv.z, wv.w};
            #pragma unroll
            for (int r = 0; r < TM; r++)
                #pragma unroll
                for (int n = 0; n < TN; n++)
                    acc[r][n] = fmaf(a_[r], w_[n], acc[r][n]);
        }
        __syncthreads();
    }

    #pragma unroll
    for (int r = 0; r < TM; r++) {
        int row = m0 + ty * TM + r;
        if (row < M) {
            float4 v = make_float4(acc[r][0], acc[r][1], acc[r][2], acc[r][3]);
            *(float4*)(C + (size_t)row * NCOL + tx * TN) = v;
        }
    }

    float4 a1v = *(const float4*)(asrc + tx * TN);
    float4 a2v = *(const float4*)(adst + tx * TN);
    float p1[TM], p2[TM];
    #pragma unroll
    for (int r = 0; r < TM; r++) {
        p1[r] = acc[r][0] * a1v.x + acc[r][1] * a1v.y + acc[r][2] * a1v.z + acc[r][3] * a1v.w;
        p2[r] = acc[r][0] * a2v.x + acc[r][1] * a2v.y + acc[r][2] * a2v.z + acc[r][3] * a2v.w;
    }
    #pragma unroll
    for (int o = TX / 2; o; o >>= 1) {
        #pragma unroll
        for (int r = 0; r < TM; r++) {
            p1[r] += __shfl_xor_sync(FULLM, p1[r], o);
            p2[r] += __shfl_xor_sync(FULLM, p2[r], o);
        }
    }
    if (tx == 0) {
        #pragma unroll
        for (int r = 0; r < TM; r++) {
            int row = m0 + ty * TM + r;
            if (row < M) { ssrc[row] = p1[r]; sdst[row] = p2[r]; }
        }
    }
}

// ---------------- layer-1 agg: online-softmax, fp16 h gathers (verbatim R9) ----------------
__global__ void k_aggH(const __half* __restrict__ h,
                       const float* __restrict__ ssrc, const float* __restrict__ sdst,
                       const float* __restrict__ bias, float* __restrict__ out) {
    int node = (blockIdx.x * blockDim.x + threadIdx.x) >> 5;
    if (node >= N_NODES) return;
    int lane = threadIdx.x & 31;
    int beg = g_off[node], end = g_off[node + 1];
    float sd = sdst[node];

    float m = -FLT_MAX, s = 0.f;
    float acc0 = 0.f, acc1 = 0.f, acc2 = 0.f, acc3 = 0.f;

    for (int c0 = beg; c0 < end; c0 += 32) {
        int n = min(32, end - c0);
        float e = -FLT_MAX; int cs = 0;
        if (lane < n) {
            cs = g_col[c0 + lane];
            float t = ssrc[cs] + sd;
            e = (t > 0.f) ? t : NEG_SLOPE * t;
        }
        float cm = e;
        #pragma unroll
        for (int o = 16; o; o >>= 1) cm = fmaxf(cm, __shfl_xor_sync(FULLM, cm, o));
        float mn = fmaxf(m, cm);
        float scale = __expf(m - mn);
        s *= scale;
        acc0 *= scale; acc1 *= scale; acc2 *= scale; acc3 *= scale;

        float w = (lane < n) ? __expf(e - mn) : 0.f;
        float ws = w;
        #pragma unroll
        for (int o = 16; o; o >>= 1) ws += __shfl_xor_sync(FULLM, ws, o);
        s += ws;
        m = mn;

        int k = 0;
        for (; k + 4 <= n; k += 4) {
            float w0 = __shfl_sync(FULLM, w, k);
            float w1 = __shfl_sync(FULLM, w, k + 1);
            float w2 = __shfl_sync(FULLM, w, k + 2);
            float w3 = __shfl_sync(FULLM, w, k + 3);
            int s0 = __shfl_sync(FULLM, cs, k);
            int s1 = __shfl_sync(FULLM, cs, k + 1);
            int s2 = __shfl_sync(FULLM, cs, k + 2);
            int s3 = __shfl_sync(FULLM, cs, k + 3);
            uint2 r0 = *(const uint2*)(h + (size_t)s0 * HID + lane * 4);
            uint2 r1 = *(const uint2*)(h + (size_t)s1 * HID + lane * 4);
            uint2 r2 = *(const uint2*)(h + (size_t)s2 * HID + lane * 4);
            uint2 r3 = *(const uint2*)(h + (size_t)s3 * HID + lane * 4);
            const __half* p0 = reinterpret_cast<const __half*>(&r0);
            const __half* p1 = reinterpret_cast<const __half*>(&r1);
            const __half* p2 = reinterpret_cast<const __half*>(&r2);
            const __half* p3 = reinterpret_cast<const __half*>(&r3);
            acc0 = fmaf(w0, __half2float(p0[0]), acc0);
            acc1 = fmaf(w0, __half2float(p0[1]), acc1);
            acc2 = fmaf(w0, __half2float(p0[2]), acc2);
            acc3 = fmaf(w0, __half2float(p0[3]), acc3);
            acc0 = fmaf(w1, __half2float(p1[0]), acc0);
            acc1 = fmaf(w1, __half2float(p1[1]), acc1);
            acc2 = fmaf(w1, __half2float(p1[2]), acc2);
            acc3 = fmaf(w1, __half2float(p1[3]), acc3);
            acc0 = fmaf(w2, __half2float(p2[0]), acc0);
            acc1 = fmaf(w2, __half2float(p2[1]), acc1);
            acc2 = fmaf(w2, __half2float(p2[2]), acc2);
            acc3 = fmaf(w2, __half2float(p2[3]), acc3);
            acc0 = fmaf(w3, __half2float(p3[0]), acc0);
            acc1 = fmaf(w3, __half2float(p3[1]), acc1);
            acc2 = fmaf(w3, __half2float(p3[2]), acc2);
            acc3 = fmaf(w3, __half2float(p3[3]), acc3);
        }
        for (; k < n; k++) {
            float w0 = __shfl_sync(FULLM, w, k);
            int s0 = __shfl_sync(FULLM, cs, k);
            uint2 r0 = *(const uint2*)(h + (size_t)s0 * HID + lane * 4);
            const __half* p0 = reinterpret_cast<const __half*>(&r0);
            acc0 = fmaf(w0, __half2float(p0[0]), acc0);
            acc1 = fmaf(w0, __half2float(p0[1]), acc1);
            acc2 = fmaf(w0, __half2float(p0[2]), acc2);
            acc3 = fmaf(w0, __half2float(p0[3]), acc3);
        }
    }

    float inv = 1.f / s;
    float4 bv = *(const float4*)(bias + lane * 4);
    float r0 = acc0 * inv + bv.x;
    float r1 = acc1 * inv + bv.y;
    float r2 = acc2 * inv + bv.z;
    float r3 = acc3 * inv + bv.w;
    r0 = (r0 > 0.f) ? r0 : expm1f(r0);
    r1 = (r1 > 0.f) ? r1 : expm1f(r1);
    r2 = (r2 > 0.f) ? r2 : expm1f(r2);
    r3 = (r3 > 0.f) ? r3 : expm1f(r3);
    float4 o4 = make_float4(r0, r1, r2, r3);
    *(float4*)(out + (size_t)node * HID + lane * 4) = o4;
}

// ---------------- layer-2 agg: verbatim online-softmax (fp32, F=64) ----------------
__global__ void k_agg64(const float* __restrict__ h,
                        const float* __restrict__ ssrc, const float* __restrict__ sdst,
                        const float* __restrict__ bias, float* __restrict__ out) {
    int node = (blockIdx.x * blockDim.x + threadIdx.x) >> 5;
    if (node >= N_NODES) return;
    int lane = threadIdx.x & 31;
    int beg = g_off[node], end = g_off[node + 1];
    float sd = sdst[node];

    float m = -FLT_MAX, s = 0.f;
    float acc0 = 0.f, acc1 = 0.f;

    for (int c0 = beg; c0 < end; c0 += 32) {
        int n = min(32, end - c0);
        float e = -FLT_MAX; int cs = 0;
        if (lane < n) {
            cs = g_col[c0 + lane];
            float t = ssrc[cs] + sd;
            e = (t > 0.f) ? t : NEG_SLOPE * t;
        }
        float cm = e;
        #pragma unroll
        for (int o = 16; o; o >>= 1) cm = fmaxf(cm, __shfl_xor_sync(FULLM, cm, o));
        float mn = fmaxf(m, cm);
        float scale = __expf(m - mn);
        s *= scale;
        acc0 *= scale; acc1 *= scale;

        float w = (lane < n) ? __expf(e - mn) : 0.f;
        float ws = w;
        #pragma unroll
        for (int o = 16; o; o >>= 1) ws += __shfl_xor_sync(FULLM, ws, o);
        s += ws;
        m = mn;

        int k = 0;
        for (; k + 4 <= n; k += 4) {
            float w0 = __shfl_sync(FULLM, w, k);
            float w1 = __shfl_sync(FULLM, w, k + 1);
            float w2 = __shfl_sync(FULLM, w, k + 2);
            float w3 = __shfl_sync(FULLM, w, k + 3);
            int s0 = __shfl_sync(FULLM, cs, k);
            int s1 = __shfl_sync(FULLM, cs, k + 1);
            int s2 = __shfl_sync(FULLM, cs, k + 2);
            int s3 = __shfl_sync(FULLM, cs, k + 3);
            float2 v0 = *(const float2*)(h + (size_t)s0 * OUTD + lane * 2);
            float2 v1 = *(const float2*)(h + (size_t)s1 * OUTD + lane * 2);
            float2 v2 = *(const float2*)(h + (size_t)s2 * OUTD + lane * 2);
            float2 v3 = *(const float2*)(h + (size_t)s3 * OUTD + lane * 2);
            acc0 = fmaf(w0, v0.x, acc0); acc1 = fmaf(w0, v0.y, acc1);
            acc0 = fmaf(w1, v1.x, acc0); acc1 = fmaf(w1, v1.y, acc1);
            acc0 = fmaf(w2, v2.x, acc0); acc1 = fmaf(w2, v2.y, acc1);
            acc0 = fmaf(w3, v3.x, acc0); acc1 = fmaf(w3, v3.y, acc1);
        }
        for (; k < n; k++) {
            float w0 = __shfl_sync(FULLM, w, k);
            int s0 = __shfl_sync(FULLM, cs, k);
            float2 v0 = *(const float2*)(h + (size_t)s0 * OUTD + lane * 2);
            acc0 = fmaf(w0, v0.x, acc0); acc1 = fmaf(w0, v0.y, acc1);
        }
    }

    float inv = 1.f / s;
    float2 bv = *(const float2*)(bias + lane * 2);
    float2 o2 = make_float2(acc0 * inv + bv.x, acc1 * inv + bv.y);
    *(float2*)(out + (size_t)node * OUTD + lane * 2) = o2;
}

// ---------------- final copy (staged result -> d_out), streaming ----------------
__global__ void k_copy(const float* __restrict__ src, float* __restrict__ dst) {
    int i = blockIdx.x * blockDim.x + threadIdx.x;
    if (i < N_NODES * (OUTD / 4)) ((float4*)dst)[i] = ((const float4*)src)[i];
}

// ---------------- launch ----------------
extern "C" void kernel_launch(void* const* d_in, const int* in_sizes, int n_in,
                              void* d_out, int out_size) {
    const float* x   = (const float*)d_in[0];
    const int*   ei  = (const int*)d_in[1];
    const float* W1  = (const float*)d_in[2];
    const float* a1s = (const float*)d_in[3];
    const float* a1d = (const float*)d_in[4];
    const float* b1  = (const float*)d_in[5];
    const float* W2  = (const float*)d_in[6];
    const float* a2s = (const float*)d_in[7];
    const float* a2d = (const float*)d_in[8];
    const float* b2  = (const float*)d_in[9];

    // d_out (device, 25.6 MB), sequential phases:
    //   1: h1 fp16 [N,128] — written by k_gemm1_mma, gathered by k_aggH
    //   2: h2 fp32 [N,64]  — written by gemm2, gathered by k_agg64
    //   3: final output fp32 — written by k_copy
    __half* h1h = (__half*)d_out;
    float*  h2  = (float*)d_out;
    float*  out = (float*)d_out;

    const int nodeBlk = (N_NODES + 255) / 256;
    const int edgeBlk = (ETOT + 255) / 256;
    const int warpBlk = (N_NODES * 32 + 255) / 256;
    const int g1Blk   = (N_NODES + 63) / 64;     // BM=64
    const int g2Blk   = (N_NODES + 127) / 128;   // BM=128
    const int cpBlk   = (N_NODES * (OUTD / 4) + 255) / 256;

    k_zeroA<<<nodeBlk, 256>>>();                                             // 0
    k_count<<<edgeBlk, 256>>>(ei);                                           // 1
    k_zeroB<<<nodeBlk, 256>>>();                                             // 2
    k_gemm1_mma<<<g1Blk, 256>>>(x, W1, h1h, a1s, a1d,
                                g_ssrc, g_sdst, N_NODES);                    // 3 <- ncu
    k_scan1<<<SCAN_NB, 256>>>();                                             // 4
    k_scan2<<<1, 512>>>(SCAN_NB);                                            // 5
    k_scan3<<<SCAN_NB, 256>>>();                                             // 6
    k_fill<<<edgeBlk, 256>>>(ei);                                            // 7
    k_aggH<<<warpBlk, 256>>>(h1h, g_ssrc, g_sdst, b1, g_o1);                 // 8
    k_gemm<HID, OUTD, 128><<<g2Blk, 256>>>(g_o1, W2, h2, a2s, a2d,
                                           g_ssrc, g_sdst, N_NODES);         // 9
    k_agg64<<<warpBlk, 256>>>(h2, g_ssrc, g_sdst, b2, g_o2);                 // 10
    k_copy<<<cpBlk, 256>>>(g_o2, out);                                       // 11
}